// round 15
// baseline (speedup 1.0000x reference)
#include <cuda_runtime.h>
#include <cuda_bf16.h>
#include <stdint.h>

// Problem constants
#define TT 6
#define BB 8
#define CC 192
#define HH 112
#define WW 112
#define KK 3
#define H0 56
#define W0 56
#define HWPIX (HH*WW)          // 12544
#define PIX (H0*W0)            // 3136
#define NN (TT*KK)             // 18 nodes
#define CG 8                   // channels per block in streaming sections
#define NCG (CC/CG)            // 24 channel groups
#define NPOOLB (TT*BB*NCG)     // 1152 pool blocks
#define POOLB_PER_B (TT*NCG)   // 144 pool blocks per batch
#define GCNB_PER_B  NN         // 18 gcn blocks per batch
#define SEG (POOLB_PER_B + GCNB_PER_B + POOLB_PER_B)   // 306 per full segment
#define NBLOCKS (CC + POOLB_PER_B + 7*SEG + GCNB_PER_B + POOLB_PER_B) // 2640

// Scratch (static device globals — no allocation)
__device__ float g_feat[BB*NN*CC];          // node features [B][N=T*K][C]
__device__ float g_Wc[CC*CC];               // W_emb^T @ W_gcn
__device__ float g_outk[BB*NN*CC];          // GCN output [B][N][C]
__device__ int   g_cnt_pool[BB] = {};       // per-batch pool completion
__device__ int   g_cnt_wc      = 0;
__device__ int   g_cnt_gcn[BB] = {};        // per-batch gcn completion
__device__ int   g_cnt_scat    = 0;

// Bid order (FIFO dispatch): wc | pool(b0) | for k=0..6: pool(b_{k+1}), gcn(b_k),
// scat(b_k) | gcn(b7), scat(b7).  scatter(b) thus runs one epoch after pool(b),
// overlapped with pool(b+1) -> scatter's x reads partially hit L2.
// __launch_bounds__(256,4) guarantees >=4 blocks/SM (592 resident) so the b0
// dependency chain (192+144+144+18+94=592) is co-resident: no deadlock.
__global__ void __launch_bounds__(256, 4)
mega_kernel(const float* __restrict__ x,
            const int* __restrict__ masks,
            const float* __restrict__ W_emb,
            const float* __restrict__ W_gcn,
            const float* __restrict__ b_gcn,
            float* __restrict__ out) {
    __shared__ float mf[3][PIX];
    __shared__ float red_s[8][24];

    const int tid = threadIdx.x;

    // ---- decode bid -> (role, batch, r/n) ----
    int v = blockIdx.x;
    int role;        // 0=wc, 1=pool, 2=gcn, 3=scatter
    int b = 0, r = 0;
    if (v < CC) {
        role = 0; r = v;
    } else {
        v -= CC;
        if (v < POOLB_PER_B) {
            role = 1; b = 0; r = v;
        } else {
            v -= POOLB_PER_B;
            int k = v / SEG;                 // 0..7 (last segment is short)
            int o = v - k * SEG;
            if (k < 7) {
                if (o < POOLB_PER_B)                    { role = 1; b = k + 1; r = o; }
                else if (o < POOLB_PER_B + GCNB_PER_B)  { role = 2; b = k;     r = o - POOLB_PER_B; }
                else                                    { role = 3; b = k;     r = o - POOLB_PER_B - GCNB_PER_B; }
            } else {
                if (o < GCNB_PER_B)                     { role = 2; b = 7;     r = o; }
                else                                    { role = 3; b = 7;     r = o - GCNB_PER_B; }
            }
        }
    }

    // =====================================================================
    if (role == 0) {
        // ---------------- WC block: Wc[c][e] = sum_d W_emb[d][c]*W_gcn[d][e]
        int c = r;
        if (tid < CC) mf[0][tid] = W_emb[(size_t)tid * CC + c];
        __syncthreads();
        if (tid < CC) {
            int e = tid;
            float acc = 0.f;
            #pragma unroll 8
            for (int d = 0; d < CC; d++)
                acc += mf[0][d] * __ldg(&W_gcn[(size_t)d * CC + e]);
            g_Wc[c*CC + e] = acc;
        }
        __syncthreads();
        if (tid == 0) { __threadfence(); atomicAdd(&g_cnt_wc, 1); }

    // =====================================================================
    } else if (role == 1) {
        // ---------------- POOL block (measured-best body) -----------------
        int t  = r / NCG;
        int cg = r % NCG;

        const int* mp = masks + ((size_t)(b*TT + t) * KK) * PIX;
        for (int i = tid; i < PIX; i += 256) {
            mf[0][i] = (float)(mp[i] & 1);
            mf[1][i] = (float)(mp[PIX + i] & 1);
            mf[2][i] = (float)(mp[2*PIX + i] & 1);
        }
        __syncthreads();

        const float* xbase = x + ((size_t)(t*BB + b)*CC + cg*CG) * HWPIX;

        float acc[CG][3];
        #pragma unroll
        for (int cc = 0; cc < CG; cc++) {
            acc[cc][0] = 0.f; acc[cc][1] = 0.f; acc[cc][2] = 0.f;
        }

        for (int i4 = tid; i4 < HWPIX/4; i4 += 256) {
            int lin = i4 * 4;
            int h = lin / WW;
            int w = lin - h * WW;
            int mb = (h >> 1) * W0 + (w >> 1);
            float2 m0 = *(const float2*)&mf[0][mb];
            float2 m1 = *(const float2*)&mf[1][mb];
            float2 m2 = *(const float2*)&mf[2][mb];
            #pragma unroll
            for (int cc = 0; cc < CG; cc++) {
                float4 vv = *(const float4*)(xbase + (size_t)cc*HWPIX + lin);
                float p0 = vv.x + vv.y, p1 = vv.z + vv.w;
                acc[cc][0] += p0 * m0.x + p1 * m0.y;
                acc[cc][1] += p0 * m1.x + p1 * m1.y;
                acc[cc][2] += p0 * m2.x + p1 * m2.y;
            }
        }

        int warp = tid >> 5, lane = tid & 31;
        #pragma unroll
        for (int cc = 0; cc < CG; cc++) {
            #pragma unroll
            for (int k = 0; k < 3; k++) {
                float s = acc[cc][k];
                #pragma unroll
                for (int off = 16; off; off >>= 1)
                    s += __shfl_down_sync(0xFFFFFFFFu, s, off);
                if (lane == 0) red_s[warp][cc*3 + k] = s;
            }
        }
        __syncthreads();
        if (tid < 24) {
            float s = 0.f;
            #pragma unroll
            for (int w8 = 0; w8 < 8; w8++) s += red_s[w8][tid];
            int cc = tid / 3, k = tid % 3;
            int c = cg * CG + cc;
            g_feat[((size_t)(b*TT + t) * KK + k) * CC + c] = s * (1.0f / (float)HWPIX);
        }
        __syncthreads();
        if (tid == 0) { __threadfence(); atomicAdd(&g_cnt_pool[b], 1); }

    // =====================================================================
    } else if (role == 2) {
        // ---------------- GCN block (re-associated fused form) -----------
        int n = r;

        float* node_s = &mf[0][0];          // NN*CC = 3456 floats
        float* adj_s  = &red_s[0][0];       // 18 floats
        float* z_s    = &mf[0][NN*CC];      // 192 floats

        if (tid == 0) {
            while (atomicAdd(&g_cnt_pool[b], 0) < POOLB_PER_B) __nanosleep(128);
            while (atomicAdd(&g_cnt_wc, 0) < CC) __nanosleep(128);
        }
        __syncthreads();

        const float* fb = g_feat + (size_t)b * NN * CC;
        for (int j = tid; j < NN*CC; j += 256)
            node_s[j] = fb[j];
        __syncthreads();

        int warp = tid >> 5, lane = tid & 31;
        if (warp < 6) {
            #pragma unroll
            for (int q = 0; q < 3; q++) {
                int m = warp * 3 + q;
                float s = 0.f;
                #pragma unroll
                for (int j = 0; j < 6; j++) {
                    int c = lane + 32*j;
                    s += node_s[n*CC + c] * node_s[m*CC + c];
                }
                #pragma unroll
                for (int off = 16; off; off >>= 1)
                    s += __shfl_down_sync(0xFFFFFFFFu, s, off);
                if (lane == 0) adj_s[m] = s;
            }
        }
        __syncthreads();

        if (tid == 0) {
            float mx = -1e30f;
            #pragma unroll
            for (int m = 0; m < NN; m++) mx = fmaxf(mx, adj_s[m]);
            float sm = 0.f;
            #pragma unroll
            for (int m = 0; m < NN; m++) { float e = expf(adj_s[m] - mx); adj_s[m] = e; sm += e; }
            float inv = 1.0f / sm;
            #pragma unroll
            for (int m = 0; m < NN; m++) adj_s[m] *= inv;
        }
        __syncthreads();

        if (tid < CC) {
            float zc = 0.f;
            #pragma unroll
            for (int m = 0; m < NN; m++)
                zc += adj_s[m] * node_s[m*CC + tid];
            z_s[tid] = zc;
        }
        __syncthreads();

        if (tid < CC) {
            int e = tid;
            float o = __ldg(&b_gcn[e]);
            #pragma unroll 8
            for (int c = 0; c < CC; c++)
                o += z_s[c] * __ldg(&g_Wc[c*CC + e]);
            g_outk[((size_t)b*NN + n)*CC + e] = o;
        }
        __syncthreads();
        if (tid == 0) { __threadfence(); atomicAdd(&g_cnt_gcn[b], 1); }

    // =====================================================================
    } else {
        // ---------------- SCATTER block (measured-best body) -------------
        int t  = r / NCG;
        int cg = r % NCG;

        // mask fill FIRST (independent of gcn) — hides the gcn tail
        const int* mp = masks + ((size_t)(b*TT + t) * KK) * PIX;
        for (int i = tid; i < PIX; i += 256) {
            mf[0][i] = (float)(mp[i] & 1);
            mf[1][i] = (float)(mp[PIX + i] & 1);
            mf[2][i] = (float)(mp[2*PIX + i] & 1);
        }

        if (tid == 0) {
            while (atomicAdd(&g_cnt_gcn[b], 0) < GCNB_PER_B) __nanosleep(128);
        }
        __syncthreads();

        if (tid < CG*3) {
            int cc = tid / 3, k = tid % 3;
            red_s[0][tid] = g_outk[((size_t)(b*TT + t) * KK + k) * CC + cg*CG + cc];
        }
        __syncthreads();

        float r3[CG][3];
        #pragma unroll
        for (int cc = 0; cc < CG; cc++) {
            r3[cc][0] = red_s[0][cc*3 + 0];
            r3[cc][1] = red_s[0][cc*3 + 1];
            r3[cc][2] = red_s[0][cc*3 + 2];
        }

        size_t plane0 = ((size_t)(t*BB + b)*CC + cg*CG) * HWPIX;
        const float* xbase = x + plane0;
        float*       obase = out + plane0;

        for (int i4 = tid; i4 < HWPIX/4; i4 += 256) {
            int lin = i4 * 4;
            int h = lin / WW;
            int w = lin - h * WW;
            int mb = (h >> 1) * W0 + (w >> 1);
            float2 m0 = *(const float2*)&mf[0][mb];
            float2 m1 = *(const float2*)&mf[1][mb];
            float2 m2 = *(const float2*)&mf[2][mb];
            #pragma unroll
            for (int cc = 0; cc < CG; cc++) {
                float4 vv = *(const float4*)(xbase + (size_t)cc*HWPIX + lin);
                float c0 = r3[cc][0]*m0.x + r3[cc][1]*m1.x + r3[cc][2]*m2.x;
                float c1 = r3[cc][0]*m0.y + r3[cc][1]*m1.y + r3[cc][2]*m2.y;
                float4 o;
                o.x = vv.x + c0; o.y = vv.y + c0;
                o.z = vv.z + c1; o.w = vv.w + c1;
                *(float4*)(obase + (size_t)cc*HWPIX + lin) = o;
            }
        }

        // last scatter block resets all counters for the next graph replay
        __syncthreads();
        if (tid == 0) {
            __threadfence();
            int done = atomicAdd(&g_cnt_scat, 1);
            if (done == NPOOLB - 1) {
                #pragma unroll
                for (int i = 0; i < BB; i++) { g_cnt_pool[i] = 0; g_cnt_gcn[i] = 0; }
                g_cnt_wc   = 0;
                g_cnt_scat = 0;
                __threadfence();
            }
        }
    }
}

// ---------------------------------------------------------------------------
extern "C" void kernel_launch(void* const* d_in, const int* in_sizes, int n_in,
                              void* d_out, int out_size) {
    const float* x      = (const float*)d_in[0];
    const int*   masks  = (const int*)  d_in[1];
    const float* W_emb  = (const float*)d_in[2];
    const float* W_gcn  = (const float*)d_in[3];
    const float* b_gcn  = (const float*)d_in[4];
    float* out = (float*)d_out;

    mega_kernel<<<NBLOCKS, 256>>>(x, masks, W_emb, W_gcn, b_gcn, out);
}

// round 16
// speedup vs baseline: 1.1251x; 1.1251x over previous
#include <cuda_runtime.h>
#include <cuda_bf16.h>
#include <stdint.h>

// Problem constants
#define TT 6
#define BB 8
#define CC 192
#define HH 112
#define WW 112
#define KK 3
#define H0 56
#define W0 56
#define HWPIX (HH*WW)          // 12544
#define PIX (H0*W0)            // 3136
#define NN (TT*KK)             // 18 nodes
#define CG 8                   // channels per block in streaming sections
#define NCG (CC/CG)            // 24 channel groups
#define NPOOLB (TT*BB*NCG)     // 1152 pool blocks
#define POOLB_PER_B (TT*NCG)   // 144 pool blocks per batch
#define GCNB_PER_B  NN         // 18 gcn blocks per batch

// Block ranges (dispatch is FIFO in bid). ORDER = wc, pool(batch-major),
// gcn(batch-major), scatter(batch-major) — the R14 measured-best layout.
#define B_WC0     0
#define B_POOL0   CC                     // 192
#define B_GCN0    (CC + NPOOLB)          // 1344
#define B_SCAT0   (B_GCN0 + NN*BB)       // 1488
#define NBLOCKS   (B_SCAT0 + NPOOLB)     // 2640

// Scratch (static device globals — no allocation)
__device__ float g_feat[BB*NN*CC];          // node features [B][N=T*K][C]
__device__ float g_Wc[CC*CC];               // W_emb^T @ W_gcn
__device__ float g_outk[BB*NN*CC];          // GCN output [B][N][C]
__device__ int   g_cnt_pool[BB] = {};       // per-batch pool completion
__device__ int   g_cnt_wc      = 0;
__device__ int   g_cnt_gcn[BB] = {};        // per-batch gcn completion
__device__ int   g_cnt_scat    = 0;

__global__ __launch_bounds__(256) void mega_kernel(const float* __restrict__ x,
                                                   const int* __restrict__ masks,
                                                   const float* __restrict__ W_emb,
                                                   const float* __restrict__ W_gcn,
                                                   const float* __restrict__ b_gcn,
                                                   float* __restrict__ out) {
    // One shared buffer, aliased per role.
    __shared__ float mf[3][PIX];
    __shared__ float red_s[8][24];

    const int bid = blockIdx.x;
    const int tid = threadIdx.x;

    // =====================================================================
    if (bid < B_POOL0) {
        // ---------------- WC block: Wc[c][e] = sum_d W_emb[d][c]*W_gcn[d][e]
        int c = bid;
        if (tid < CC) mf[0][tid] = W_emb[(size_t)tid * CC + c];
        __syncthreads();
        if (tid < CC) {
            int e = tid;
            float acc = 0.f;
            #pragma unroll 8
            for (int d = 0; d < CC; d++)
                acc += mf[0][d] * __ldg(&W_gcn[(size_t)d * CC + e]);
            g_Wc[c*CC + e] = acc;
        }
        __syncthreads();
        if (tid == 0) { __threadfence(); atomicAdd(&g_cnt_wc, 1); }

    // =====================================================================
    } else if (bid < B_GCN0) {
        // ---------------- POOL block (batch-major dispatch, forward order)
        int pb = bid - B_POOL0;
        int b  = pb / POOLB_PER_B;          // batch outermost -> b0 finishes first
        int r  = pb % POOLB_PER_B;
        int t  = r / NCG;
        int cg = r % NCG;

        const int* mp = masks + ((size_t)(b*TT + t) * KK) * PIX;
        for (int i = tid; i < PIX; i += 256) {
            mf[0][i] = (float)(mp[i] & 1);
            mf[1][i] = (float)(mp[PIX + i] & 1);
            mf[2][i] = (float)(mp[2*PIX + i] & 1);
        }
        __syncthreads();

        const float* xbase = x + ((size_t)(t*BB + b)*CC + cg*CG) * HWPIX;

        float acc[CG][3];
        #pragma unroll
        for (int cc = 0; cc < CG; cc++) {
            acc[cc][0] = 0.f; acc[cc][1] = 0.f; acc[cc][2] = 0.f;
        }

        for (int i4 = tid; i4 < HWPIX/4; i4 += 256) {
            int lin = i4 * 4;
            int h = lin / WW;
            int w = lin - h * WW;
            int mb = (h >> 1) * W0 + (w >> 1);
            float2 m0 = *(const float2*)&mf[0][mb];
            float2 m1 = *(const float2*)&mf[1][mb];
            float2 m2 = *(const float2*)&mf[2][mb];
            #pragma unroll
            for (int cc = 0; cc < CG; cc++) {
                float4 v = *(const float4*)(xbase + (size_t)cc*HWPIX + lin);
                float p0 = v.x + v.y, p1 = v.z + v.w;
                acc[cc][0] += p0 * m0.x + p1 * m0.y;
                acc[cc][1] += p0 * m1.x + p1 * m1.y;
                acc[cc][2] += p0 * m2.x + p1 * m2.y;
            }
        }

        int warp = tid >> 5, lane = tid & 31;
        #pragma unroll
        for (int cc = 0; cc < CG; cc++) {
            #pragma unroll
            for (int k = 0; k < 3; k++) {
                float s = acc[cc][k];
                #pragma unroll
                for (int off = 16; off; off >>= 1)
                    s += __shfl_down_sync(0xFFFFFFFFu, s, off);
                if (lane == 0) red_s[warp][cc*3 + k] = s;
            }
        }
        __syncthreads();
        if (tid < 24) {
            float s = 0.f;
            #pragma unroll
            for (int w8 = 0; w8 < 8; w8++) s += red_s[w8][tid];
            int cc = tid / 3, k = tid % 3;
            int c = cg * CG + cc;
            g_feat[((size_t)(b*TT + t) * KK + k) * CC + c] = s * (1.0f / (float)HWPIX);
        }
        __syncthreads();
        if (tid == 0) { __threadfence(); atomicAdd(&g_cnt_pool[b], 1); }

    // =====================================================================
    } else if (bid < B_SCAT0) {
        // ---------------- GCN block (re-associated fused form) -----------
        int idx = bid - B_GCN0;
        int b = idx / NN, n = idx % NN;     // batch-major

        float* node_s = &mf[0][0];          // NN*CC = 3456 floats
        float* adj_s  = &red_s[0][0];       // 18 floats
        float* z_s    = &mf[0][NN*CC];      // 192 floats

        // wait for THIS batch's pool blocks + wc
        if (tid == 0) {
            while (atomicAdd(&g_cnt_pool[b], 0) < POOLB_PER_B) __nanosleep(128);
            while (atomicAdd(&g_cnt_wc, 0) < CC) __nanosleep(128);
        }
        __syncthreads();

        const float* fb = g_feat + (size_t)b * NN * CC;
        for (int j = tid; j < NN*CC; j += 256)
            node_s[j] = fb[j];
        __syncthreads();

        // gram row n: warps 0..5, warp w handles m = w*3 + q
        int warp = tid >> 5, lane = tid & 31;
        if (warp < 6) {
            #pragma unroll
            for (int q = 0; q < 3; q++) {
                int m = warp * 3 + q;
                float s = 0.f;
                #pragma unroll
                for (int j = 0; j < 6; j++) {
                    int c = lane + 32*j;
                    s += node_s[n*CC + c] * node_s[m*CC + c];
                }
                #pragma unroll
                for (int off = 16; off; off >>= 1)
                    s += __shfl_down_sync(0xFFFFFFFFu, s, off);
                if (lane == 0) adj_s[m] = s;
            }
        }
        __syncthreads();

        if (tid == 0) {
            float mx = -1e30f;
            #pragma unroll
            for (int m = 0; m < NN; m++) mx = fmaxf(mx, adj_s[m]);
            float sm = 0.f;
            #pragma unroll
            for (int m = 0; m < NN; m++) { float e = expf(adj_s[m] - mx); adj_s[m] = e; sm += e; }
            float inv = 1.0f / sm;
            #pragma unroll
            for (int m = 0; m < NN; m++) adj_s[m] *= inv;
        }
        __syncthreads();

        // z[c] = sum_m adj[m] * node[m][c]
        if (tid < CC) {
            float zc = 0.f;
            #pragma unroll
            for (int m = 0; m < NN; m++)
                zc += adj_s[m] * node_s[m*CC + tid];
            z_s[tid] = zc;
        }
        __syncthreads();

        // out[e] = b_gcn[e] + sum_c z[c] * Wc[c][e]
        if (tid < CC) {
            int e = tid;
            float o = __ldg(&b_gcn[e]);
            #pragma unroll 8
            for (int c = 0; c < CC; c++)
                o += z_s[c] * __ldg(&g_Wc[c*CC + e]);
            g_outk[((size_t)b*NN + n)*CC + e] = o;
        }
        __syncthreads();
        if (tid == 0) { __threadfence(); atomicAdd(&g_cnt_gcn[b], 1); }

    // =====================================================================
    } else {
        // ---------------- SCATTER block (MRU-first traversal) ------------
        // Plane order reversed vs pool (last-pooled plane scattered first)
        // and inner loop descending: reads the freshest L2 lines of x_b
        // before the concurrent pool(b+1..) stream evicts them.
        int idx = bid - B_SCAT0;
        int b  = idx / POOLB_PER_B;         // batch outermost -> pipeline
        int r  = (POOLB_PER_B - 1) - (idx % POOLB_PER_B);   // reversed
        int t  = r / NCG;
        int cg = r % NCG;

        // mask fill FIRST (independent of gcn) — hides the gcn tail
        const int* mp = masks + ((size_t)(b*TT + t) * KK) * PIX;
        for (int i = tid; i < PIX; i += 256) {
            mf[0][i] = (float)(mp[i] & 1);
            mf[1][i] = (float)(mp[PIX + i] & 1);
            mf[2][i] = (float)(mp[2*PIX + i] & 1);
        }

        // wait for THIS batch's gcn blocks only
        if (tid == 0) {
            while (atomicAdd(&g_cnt_gcn[b], 0) < GCNB_PER_B) __nanosleep(128);
        }
        __syncthreads();

        if (tid < CG*3) {
            int cc = tid / 3, k = tid % 3;
            red_s[0][tid] = g_outk[((size_t)(b*TT + t) * KK + k) * CC + cg*CG + cc];
        }
        __syncthreads();

        float r3[CG][3];
        #pragma unroll
        for (int cc = 0; cc < CG; cc++) {
            r3[cc][0] = red_s[0][cc*3 + 0];
            r3[cc][1] = red_s[0][cc*3 + 1];
            r3[cc][2] = red_s[0][cc*3 + 2];
        }

        size_t plane0 = ((size_t)(t*BB + b)*CC + cg*CG) * HWPIX;
        const float* xbase = x + plane0;
        float*       obase = out + plane0;

        // descending traversal (MRU-first); per-warp coalescing unchanged
        for (int i4 = (HWPIX/4 - 256) + tid; i4 >= 0; i4 -= 256) {
            int lin = i4 * 4;
            int h = lin / WW;
            int w = lin - h * WW;
            int mb = (h >> 1) * W0 + (w >> 1);
            float2 m0 = *(const float2*)&mf[0][mb];
            float2 m1 = *(const float2*)&mf[1][mb];
            float2 m2 = *(const float2*)&mf[2][mb];
            #pragma unroll
            for (int cc = CG-1; cc >= 0; cc--) {
                float4 v = *(const float4*)(xbase + (size_t)cc*HWPIX + lin);
                float c0 = r3[cc][0]*m0.x + r3[cc][1]*m1.x + r3[cc][2]*m2.x;
                float c1 = r3[cc][0]*m0.y + r3[cc][1]*m1.y + r3[cc][2]*m2.y;
                float4 o;
                o.x = v.x + c0; o.y = v.y + c0;
                o.z = v.z + c1; o.w = v.w + c1;
                *(float4*)(obase + (size_t)cc*HWPIX + lin) = o;
            }
        }

        // last scatter block resets all counters for the next graph replay
        __syncthreads();
        if (tid == 0) {
            __threadfence();
            int done = atomicAdd(&g_cnt_scat, 1);
            if (done == NPOOLB - 1) {
                #pragma unroll
                for (int i = 0; i < BB; i++) { g_cnt_pool[i] = 0; g_cnt_gcn[i] = 0; }
                g_cnt_wc   = 0;
                g_cnt_scat = 0;
                __threadfence();
            }
        }
    }
}

// ---------------------------------------------------------------------------
extern "C" void kernel_launch(void* const* d_in, const int* in_sizes, int n_in,
                              void* d_out, int out_size) {
    const float* x      = (const float*)d_in[0];
    const int*   masks  = (const int*)  d_in[1];
    const float* W_emb  = (const float*)d_in[2];
    const float* W_gcn  = (const float*)d_in[3];
    const float* b_gcn  = (const float*)d_in[4];
    float* out = (float*)d_out;

    mega_kernel<<<NBLOCKS, 256>>>(x, masks, W_emb, W_gcn, b_gcn, out);
}